// round 7
// baseline (speedup 1.0000x reference)
#include <cuda_runtime.h>
#include <cstdint>
#include <math.h>

// Problem constants
#define NB 32     // batch
#define NP 192    // patches
#define NA 30     // attributes
#define NE 256    // embed dim
#define NK 768    // input feature dim
#define SV 193    // visual seq len
#define ST 31     // textual seq len

#define VE_OFF 0
#define TE_OFF 8192
#define PM_OFF 16384
#define AM_OFF 24576
#define SIM_OFF 32768

// Scratch
__device__ float g_patch[NB * NP * NE];    // [v][p][e]
__device__ float g_patchT[NB * NE * NP];   // [v][e][p]
__device__ float g_att[NB * NA * NE];
__device__ float g_rp[NB * NP];
__device__ float g_ra[NB * NA];
__device__ float g_G[NB * NA * 32];
__device__ float g_WT[4 * NK * NE];        // transposed weights [seg][k][n]

typedef unsigned long long ull;

__device__ __forceinline__ void fma2(ull& d, ull a, ull b) {
    asm("fma.rn.f32x2 %0, %1, %2, %3;" : "=l"(d) : "l"(a), "l"(b), "l"(d));
}
__device__ __forceinline__ ull pk2(float x, float y) {
    ull r; asm("mov.b64 %0, {%1,%2};" : "=l"(r) : "f"(x), "f"(y)); return r;
}
__device__ __forceinline__ float2 upk(ull v) {
    float2 r; asm("mov.b64 {%0,%1}, %2;" : "=f"(r.x), "=f"(r.y) : "l"(v)); return r;
}
__device__ __forceinline__ void cpa16(uint32_t s, const void* g) {
    asm volatile("cp.async.cg.shared.global [%0], [%1], 16;\n" :: "r"(s), "l"(g));
}
__device__ __forceinline__ void cpa_commit() {
    asm volatile("cp.async.commit_group;\n" ::: "memory");
}
template<int N>
__device__ __forceinline__ void cpa_wait() {
    asm volatile("cp.async.wait_group %0;\n" :: "n"(N) : "memory");
}

// ---------------------------------------------------------------------------
// Transpose the four weight matrices [256][768] -> g_WT[seg][768][256]
// ---------------------------------------------------------------------------
__global__ __launch_bounds__(256) void wt_kernel(
    const float* __restrict__ W0, const float* __restrict__ W1,
    const float* __restrict__ W2, const float* __restrict__ W3)
{
    __shared__ float ts[32][33];
    const int z = blockIdx.z;
    const float* W = (z == 0) ? W0 : (z == 1) ? W1 : (z == 2) ? W2 : W3;
    const int k0 = blockIdx.x * 32;
    const int n0 = blockIdx.y * 32;
    const int lane = threadIdx.x & 31, wid = threadIdx.x >> 5;
#pragma unroll
    for (int i = 0; i < 4; i++)
        ts[wid + 8 * i][lane] = W[(size_t)(n0 + wid + 8 * i) * NK + k0 + lane];
    __syncthreads();
    float* WT = g_WT + (size_t)z * NK * NE;
#pragma unroll
    for (int i = 0; i < 4; i++)
        WT[(size_t)(k0 + wid + 8 * i) * NE + n0 + lane] = ts[lane][wid + 8 * i];
}

// ---------------------------------------------------------------------------
// Merged projection GEMM, cp.async TRIPLE-buffered (2 tiles in flight).
// grid (4, 113): y<96 patch, y<111 att, y==111 vis cls, y==112 txt cls.
// 64m x 64n x 768k, k-chunk 32, microtile 4m x 4n (f32x2 over n).
// Dynamic smem: 3*(64*36 + 32*64) floats = 52224 B.
// ---------------------------------------------------------------------------
#define PA_SZ (64 * 36)
#define PB_SZ (32 * 64)
__global__ __launch_bounds__(256) void proj2_kernel(
    const float* __restrict__ vf, const float* __restrict__ tf,
    const float* __restrict__ b_patch, const float* __restrict__ b_att,
    const float* __restrict__ b_vis, const float* __restrict__ b_txt,
    float* __restrict__ out)
{
    extern __shared__ float psm[];

    const int y = blockIdx.y;
    int seg, my;
    if (y < 96)       { seg = 0; my = y; }
    else if (y < 111) { seg = 1; my = y - 96; }
    else if (y == 111){ seg = 2; my = 0; }
    else              { seg = 3; my = 0; }

    const int M  = (seg == 0) ? NB * NP : (seg == 1) ? NB * NA : NB;
    const int S  = (seg == 0 || seg == 2) ? SV : ST;
    const int gs = (seg == 0) ? NP : (seg == 1) ? NA : 1;
    const int off= (seg <= 1) ? 1 : 0;
    const float* X = (seg == 0 || seg == 2) ? vf : tf;
    const float* bias = (seg == 0) ? b_patch : (seg == 1) ? b_att
                       : (seg == 2) ? b_vis : b_txt;
    float* obase;
    if (seg == 0) obase = g_patch;
    else if (seg == 1) obase = g_att;
    else if (seg == 2) obase = out + VE_OFF;
    else obase = out + TE_OFF;
    const float* WT = g_WT + (size_t)seg * NK * NE;

    const int col0 = blockIdx.x * 64;
    const int row0 = my * 64;
    const int tid = threadIdx.x;
    const int tm = tid >> 4, tn = tid & 15;

    const int c1 = tid + 256;
    const int ar0 = tid >> 3,  ac0 = (tid & 7) << 2;
    const int ar1 = c1 >> 3,   ac1 = (c1 & 7) << 2;
    int gr0 = row0 + ar0; if (gr0 >= M) gr0 = M - 1;
    int gr1 = row0 + ar1; if (gr1 >= M) gr1 = M - 1;
    const float* aS0 = X + (size_t)((gr0 / gs) * S + off + gr0 % gs) * NK + ac0;
    const float* aS1 = X + (size_t)((gr1 / gs) * S + off + gr1 % gs) * NK + ac1;
    const uint32_t aD0 = (ar0 * 36 + ac0) * 4;
    const uint32_t aD1 = (ar1 * 36 + ac1) * 4;
    const int bk0 = tid >> 4, bc0 = (tid & 15) << 2;
    const int bk1 = c1 >> 4,  bc1 = (c1 & 15) << 2;
    const float* bS0 = WT + (size_t)bk0 * NE + col0 + bc0;
    const float* bS1 = WT + (size_t)bk1 * NE + col0 + bc1;
    const uint32_t bD0 = (bk0 * 64 + bc0) * 4;
    const uint32_t bD1 = (bk1 * 64 + bc1) * 4;

    const uint32_t sA = (uint32_t)__cvta_generic_to_shared(psm);
    const uint32_t sB = (uint32_t)__cvta_generic_to_shared(psm + 3 * PA_SZ);

    ull c2[4][2];
#pragma unroll
    for (int i = 0; i < 4; i++) { c2[i][0] = 0ull; c2[i][1] = 0ull; }

    // prologue: stage tiles 0 and 1
#pragma unroll
    for (int pb = 0; pb < 2; pb++) {
        const uint32_t oA = sA + pb * (PA_SZ * 4);
        const uint32_t oB = sB + pb * (PB_SZ * 4);
        const int k0 = pb * 32;
        cpa16(oA + aD0, aS0 + k0);
        cpa16(oA + aD1, aS1 + k0);
        cpa16(oB + bD0, bS0 + (size_t)k0 * NE);
        cpa16(oB + bD1, bS1 + (size_t)k0 * NE);
        cpa_commit();
    }

    for (int it = 0; it < 24; it++) {
        if (it < 22) {
            const int nb = (it + 2) % 3;
            const uint32_t oA = sA + nb * (PA_SZ * 4);
            const uint32_t oB = sB + nb * (PB_SZ * 4);
            const int k0 = (it + 2) * 32;
            cpa16(oA + aD0, aS0 + k0);
            cpa16(oA + aD1, aS1 + k0);
            cpa16(oB + bD0, bS0 + (size_t)k0 * NE);
            cpa16(oB + bD1, bS1 + (size_t)k0 * NE);
            cpa_commit();
            cpa_wait<2>();
        } else if (it == 22) {
            cpa_wait<1>();
        } else {
            cpa_wait<0>();
        }
        __syncthreads();

        const float* A = psm + (it % 3) * PA_SZ;
        const float* B = psm + 3 * PA_SZ + (it % 3) * PB_SZ;
#pragma unroll
        for (int q = 0; q < 8; q++) {
            float4 a[4];
#pragma unroll
            for (int i = 0; i < 4; i++)
                a[i] = *(const float4*)&A[(tm * 4 + i) * 36 + q * 4];
#pragma unroll
            for (int j = 0; j < 4; j++) {
                ulonglong2 bb = *(const ulonglong2*)&B[(q * 4 + j) * 64 + tn * 4];
#pragma unroll
                for (int i = 0; i < 4; i++) {
                    float av = (j == 0) ? a[i].x : (j == 1) ? a[i].y
                             : (j == 2) ? a[i].z : a[i].w;
                    ull d = pk2(av, av);
                    fma2(c2[i][0], d, bb.x);
                    fma2(c2[i][1], d, bb.y);
                }
            }
        }
        __syncthreads();
    }

    const float4 b4 = *(const float4*)&bias[col0 + tn * 4];
#pragma unroll
    for (int i = 0; i < 4; i++) {
        int r = row0 + tm * 4 + i;
        if (r < M) {
            float2 lo = upk(c2[i][0]), hi = upk(c2[i][1]);
            float4 o;
            o.x = lo.x + b4.x; o.y = lo.y + b4.y;
            o.z = hi.x + b4.z; o.w = hi.y + b4.w;
            *(float4*)&obase[(size_t)r * NE + col0 + tn * 4] = o;
        }
    }
}

// ---------------------------------------------------------------------------
// Fused prep kernel: transpose | norms | gram | means
// ---------------------------------------------------------------------------
__global__ __launch_bounds__(256) void prep_kernel(
    const int* __restrict__ att_nums, float* __restrict__ out)
{
    __shared__ float sbuf[NA * NE];
    const int r = blockIdx.x;
    const int tid = threadIdx.x;
    const int lane = tid & 31, wid = tid >> 5;

    if (r < 1536) {
        float (*ts)[33] = (float (*)[33])sbuf;
        const int v = r / 48, rem = r % 48;
        const int e0 = (rem / 6) * 32, p0 = (rem % 6) * 32;
        const float* src = g_patch + (size_t)v * NP * NE;
        float* dst = g_patchT + (size_t)v * NE * NP;
#pragma unroll
        for (int k = 0; k < 4; k++)
            ts[wid + 8 * k][lane] = src[(size_t)(p0 + wid + 8 * k) * NE + e0 + lane];
        __syncthreads();
#pragma unroll
        for (int k = 0; k < 4; k++)
            dst[(size_t)(e0 + wid + 8 * k) * NP + p0 + lane] = ts[lane][wid + 8 * k];
    } else if (r < 2424) {
        const int w = (r - 1536) * 8 + wid;
        if (w >= NB * NP + NB * NA) return;
        const float* row;
        float* dst;
        if (w < NB * NP) { row = g_patch + (size_t)w * NE; dst = &g_rp[w]; }
        else { row = g_att + (size_t)(w - NB * NP) * NE; dst = &g_ra[w - NB * NP]; }
        float4 x0 = *(const float4*)&row[lane * 4];
        float4 x1 = *(const float4*)&row[128 + lane * 4];
        float ss = x0.x * x0.x + x0.y * x0.y + x0.z * x0.z + x0.w * x0.w
                 + x1.x * x1.x + x1.y * x1.y + x1.z * x1.z + x1.w * x1.w;
#pragma unroll
        for (int o = 16; o > 0; o >>= 1) ss += __shfl_xor_sync(~0u, ss, o);
        if (lane == 0) *dst = rsqrtf(fmaxf(ss, 1e-24f));
    } else if (r < 2456) {
        const int t = r - 2424;
        const float* ap = g_att + (size_t)t * NA * NE;
        for (int i = tid; i < NA * NE; i += 256) sbuf[i] = ap[i];
        __syncthreads();
        for (int idx = tid; idx < NA * NA; idx += 256) {
            int a = idx / NA, b = idx % NA;
            const float* ra = sbuf + a * NE;
            const float* rb = sbuf + b * NE;
            float acc = 0.f;
#pragma unroll 4
            for (int e = 0; e < NE; e += 4) {
                float4 x = *(float4*)&ra[e];
                float4 y = *(float4*)&rb[e];
                acc += x.x * y.x + x.y * y.y + x.z * y.z + x.w * y.w;
            }
            g_G[t * NA * 32 + a * 32 + b] = acc;
        }
    } else {
        const int b = r - 2456;
        const int e = tid;
        float pm = 0.f;
        const float* pb = g_patch + (size_t)b * NP * NE + e;
#pragma unroll 4
        for (int p = 0; p < NP; p++) pm += pb[(size_t)p * NE];
        out[PM_OFF + b * NE + e] = pm / (float)NP;
        float am = 0.f;
        const float* ab = g_att + (size_t)b * NA * NE + e;
#pragma unroll
        for (int a = 0; a < NA; a++) am += ab[(size_t)a * NE];
        out[AM_OFF + b * NE + e] = am / (float)att_nums[b];
    }
}

// ---------------------------------------------------------------------------
// Pair kernel smem layout (floats). Total 18113 fl = 72452 B -> 3 CTAs/SM.
// Region1 (7680): s_att [30][256] during stage A; s_M [32][192] after
// (M lives in registers through stage A, so the alias is safe).
// ---------------------------------------------------------------------------
#define SA_R1   0          /* 7680 */
#define SA_A1   7680       /* 5760 : attn1 [30][192] */
#define SA_TILE 13440      /* 3136 : stage A 16x196 / stage C 12x256 */
#define SA_G    16576      /* 960 */
#define SA_RA   17536      /* 32 */
#define SA_RP   17568      /* 192 */
#define SA_PADF 17760      /* 32 */
#define SA_W2   17792      /* 32 */
#define SA_C    17824      /* 32 */
#define SA_CP   17856      /* 192 : c_a per-warp partials */
#define SA_RED  18048      /* 64 */
#define SA_AN   18112      /* 1 */
#define SMEM_F  18113
#define TILE_LD 196

// Stage C per-tile accumulate: 12 p-rows from s_ctile [12][256], 8 a's.
// (a-rows >= 30 read in-bounds garbage; their results are never consumed.)
__device__ __forceinline__ void stage_c_tile(const float* __restrict__ s_ctile,
                                             const float* __restrict__ s_A1,
                                             ull (&acc)[8][2], int e4, int a0, int p0)
{
#pragma unroll
    for (int pp = 0; pp < 12; pp += 4) {
        ulonglong2 u0 = *(const ulonglong2*)&s_ctile[(pp + 0) * NE + e4 * 4];
        ulonglong2 u1 = *(const ulonglong2*)&s_ctile[(pp + 1) * NE + e4 * 4];
        ulonglong2 u2 = *(const ulonglong2*)&s_ctile[(pp + 2) * NE + e4 * 4];
        ulonglong2 u3 = *(const ulonglong2*)&s_ctile[(pp + 3) * NE + e4 * 4];
#pragma unroll
        for (int a = 0; a < 8; a++) {
            float4 q = *(const float4*)&s_A1[(a0 + a) * NP + p0 + pp];
            ull w0 = pk2(q.x, q.x), w1 = pk2(q.y, q.y);
            ull w2 = pk2(q.z, q.z), w3 = pk2(q.w, q.w);
            fma2(acc[a][0], w0, u0.x); fma2(acc[a][1], w0, u0.y);
            fma2(acc[a][0], w1, u1.x); fma2(acc[a][1], w1, u1.y);
            fma2(acc[a][0], w2, u2.x); fma2(acc[a][1], w2, u2.y);
            fma2(acc[a][0], w3, u3.x); fma2(acc[a][1], w3, u3.y);
        }
    }
}

// ---------------------------------------------------------------------------
// Fused per-(t,v) pair kernel. 256 threads, 70.8 KB smem, 3 CTAs/SM.
// ---------------------------------------------------------------------------
__global__ __launch_bounds__(256, 3) void pair_kernel(const int* __restrict__ mask,
                                                      const int* __restrict__ att_nums,
                                                      float* __restrict__ out_sim)
{
    extern __shared__ float sm[];
    const int v = blockIdx.x, t = blockIdx.y;
    const int tid = threadIdx.x, lane = tid & 31, wid = tid >> 5;

    float* s_att  = sm + SA_R1;     // [30][256] during stage A
    float* s_M    = sm + SA_R1;     // [32][192] after stage A (alias)
    float* s_A1   = sm + SA_A1;
    float* s_tile = sm + SA_TILE;
    float* s_G    = sm + SA_G;
    float* s_ra   = sm + SA_RA;
    float* s_rp   = sm + SA_RP;
    float* s_padf = sm + SA_PADF;
    float* s_w2   = sm + SA_W2;
    float* s_c    = sm + SA_C;
    float* s_cp   = sm + SA_CP;
    float* s_red  = sm + SA_RED;
    float* s_an   = sm + SA_AN;

    // ---- preload ----
    const float* attp = g_att + (size_t)t * NA * NE;
    for (int i = tid; i < NA * NE; i += 256) s_att[i] = attp[i];
    const float* gGp = g_G + t * NA * 32;
    for (int i = tid; i < NA * 32; i += 256) s_G[i] = gGp[i];
    if (tid < NA) {
        s_ra[tid] = g_ra[t * NA + tid];
        s_padf[tid] = (mask[t * NA + tid] != 0) ? 1.f : 0.f;
    }
    if (tid < NP) s_rp[tid] = g_rp[v * NP + tid];
    if (tid == 0) s_an[0] = (float)att_nums[t];
    __syncthreads();

    const float* pbase = g_patch + (size_t)v * NP * NE;
    const float* ptv   = g_patchT + (size_t)v * NE * NP;

    // ---- Stage A: M[a][p] = att_a . patch_p. 8a x 6p microtile, e-split 2.
    // Shared 16-row tile per chunk: rows 0-7 = group0 e's, 8-15 = group1 e's.
    {
        const int eg = tid >> 7;
        const int g  = tid & 127;
        const int a0 = (g >> 5) * 8;      // a-rows >= 30 compute dead garbage
        const int p0 = (g & 31) * 6;
        const int rb = eg * 8;

        ull acc[8][3];
#pragma unroll
        for (int a = 0; a < 8; a++) { acc[a][0] = acc[a][1] = acc[a][2] = 0ull; }

        for (int c = 0; c < 16; c++) {
            // cooperative load: 16 rows x 192 p (both e-groups)
#pragma unroll
            for (int i = 0; i < 3; i++) {
                int fid = tid + 256 * i;             // 0..767
                int row = fid / 48, col = (fid % 48) * 4;
                int e = (row < 8) ? (c * 8 + row) : (128 + c * 8 + row - 8);
                *(float4*)&s_tile[row * TILE_LD + col] =
                    *(const float4*)&ptv[(size_t)e * NP + col];
            }
            __syncthreads();
            const int e0 = eg * 128 + c * 8;
#pragma unroll
            for (int e2 = 0; e2 < 8; e2 += 2) {
                float2 av[8];
#pragma unroll
                for (int a = 0; a < 8; a++)
                    av[a] = *(const float2*)&s_att[(a0 + a) * NE + e0 + e2];
#pragma unroll
                for (int j = 0; j < 2; j++) {
                    const float* tr = &s_tile[(rb + e2 + j) * TILE_LD + p0];
                    ull p01 = *(const ull*)&tr[0];
                    ull p23 = *(const ull*)&tr[2];
                    ull p45 = *(const ull*)&tr[4];
#pragma unroll
                    for (int a = 0; a < 8; a++) {
                        float aval = j ? av[a].y : av[a].x;
                        ull ad = pk2(aval, aval);
                        fma2(acc[a][0], ad, p01);
                        fma2(acc[a][1], ad, p23);
                        fma2(acc[a][2], ad, p45);
                    }
                }
            }
            __syncthreads();
        }
        // combine the two e-halves into s_M (aliases s_att; att dead now)
        if (eg == 1) {
#pragma unroll
            for (int a = 0; a < 8; a++)
#pragma unroll
                for (int jj = 0; jj < 3; jj++) {
                    float2 f = upk(acc[a][jj]);
                    *(float2*)&s_M[(a0 + a) * NP + p0 + 2 * jj] = f;
                }
        }
        __syncthreads();
        if (eg == 0) {
#pragma unroll
            for (int a = 0; a < 8; a++)
#pragma unroll
                for (int jj = 0; jj < 3; jj++) {
                    float2 f = upk(acc[a][jj]);
                    float2 o = *(float2*)&s_M[(a0 + a) * NP + p0 + 2 * jj];
                    o.x += f.x; o.y += f.y;
                    *(float2*)&s_M[(a0 + a) * NP + p0 + 2 * jj] = o;
                }
        }
        __syncthreads();
    }

    // ---- attn1: softmax over p of D = relu(M*ra*rp)*20 (warp per row) ----
    for (int r = wid; r < NA; r += 8) {
        const float ra = s_ra[r];
        float x[6];
        float mx = 0.f;
#pragma unroll
        for (int j = 0; j < 6; j++) {
            int p = lane + j * 32;
            float d = fmaxf(s_M[r * NP + p] * ra * s_rp[p], 0.f) * 20.f;
            x[j] = d; mx = fmaxf(mx, d);
        }
#pragma unroll
        for (int o = 16; o > 0; o >>= 1) mx = fmaxf(mx, __shfl_xor_sync(~0u, mx, o));
        float ssum = 0.f;
#pragma unroll
        for (int j = 0; j < 6; j++) { x[j] = __expf(x[j] - mx); ssum += x[j]; }
#pragma unroll
        for (int o = 16; o > 0; o >>= 1) ssum += __shfl_xor_sync(~0u, ssum, o);
        const float rinv = 1.f / ssum;
#pragma unroll
        for (int j = 0; j < 6; j++) s_A1[r * NP + lane + j * 32] = x[j] * rinv;
    }

    // ---- attn2 (masked softmax over a) + Gram quadratic -> w_p,
    //      fused c_a = sum_p attn2[a][p]*w_p via warp reductions ----
    if (tid < NP) {
        const int p = tid;
        const float rp = s_rp[p];
        float vv[NA];
        float mx = 0.f;
#pragma unroll
        for (int a = 0; a < NA; a++) {
            float d = fmaxf(s_M[a * NP + p] * s_ra[a] * rp, 0.f) * 20.f;
            if (s_padf[a] == 0.f) { vv[a] = d; mx = fmaxf(mx, d); }
            else                  { vv[a] = -1.f; }
        }
        float ssum = 0.f;
#pragma unroll
        for (int a = 0; a < NA; a++) {
            float e = (vv[a] < 0.f) ? 0.f : __expf(vv[a] - mx);
            vv[a] = e; ssum += e;
        }
        const float rinv = 1.f / ssum;
#pragma unroll
        for (int a = 0; a < NA; a++) vv[a] *= rinv;
        float z = 0.f;
#pragma unroll 1
        for (int b = 0; b < NA; b++) {
            const float* Gr = s_G + b * 32;
            float yb = 0.f;
#pragma unroll
            for (int a = 0; a < NA; a++) yb = fmaf(vv[a], Gr[a], yb);
            z = fmaf(yb, vv[b], z);
        }
        const float wp = rsqrtf(fmaxf(z, 1e-24f));
        // c_a partials: warps 0-5 are fully active here (NP = 6*32)
#pragma unroll
        for (int a = 0; a < NA; a++) {
            float val = vv[a] * wp;
#pragma unroll
            for (int o = 16; o > 0; o >>= 1) val += __shfl_xor_sync(~0u, val, o);
            if (lane == 0) s_cp[wid * 32 + a] = val;
        }
    }
    __syncthreads();
    if (tid < NA) {
        float cc = 0.f;
#pragma unroll
        for (int w = 0; w < 6; w++) cc += s_cp[w * 32 + tid];
        s_c[tid] = cc;
    }

    // ---- Stage C: ||attend_patch_a||^2, patch staged through 12-row tiles ----
    {
        const int e4 = tid & 63, a0 = (tid >> 6) * 8;
        ull acc[8][2];
#pragma unroll
        for (int a = 0; a < 8; a++) { acc[a][0] = 0ull; acc[a][1] = 0ull; }

        for (int pt = 0; pt < 16; pt++) {
            const int p0 = pt * 12;
#pragma unroll
            for (int i2 = 0; i2 < 3; i2++) {
                int fid = tid + 256 * i2;            // 0..767
                int row = fid >> 6, col = (fid & 63) << 2;
                *(float4*)&s_tile[row * NE + col] =
                    *(const float4*)&pbase[(size_t)(p0 + row) * NE + col];
            }
            __syncthreads();
            stage_c_tile(s_tile, s_A1, acc, e4, a0, p0);
            __syncthreads();
        }
#pragma unroll
        for (int a = 0; a < 8; a++) {
            float2 f0 = upk(acc[a][0]), f1 = upk(acc[a][1]);
            float s = f0.x * f0.x + f0.y * f0.y + f1.x * f1.x + f1.y * f1.y;
#pragma unroll
            for (int o = 16; o > 0; o >>= 1) s += __shfl_xor_sync(~0u, s, o);
            if (lane == 0) s_red[wid * 8 + a] = s;
        }
    }
    __syncthreads();
    if (tid < NA) {
        const int hh = tid >> 3, al = tid & 7;
        float ss2 = s_red[(hh * 2) * 8 + al] + s_red[(hh * 2 + 1) * 8 + al];
        s_w2[tid] = (s_padf[tid] != 0.f) ? 0.f : rsqrtf(fmaxf(ss2, 1e-24f));
    }
    __syncthreads();

    // ---- final: sim = sum_p d_p * (sum_a c_a M[a][p]) / (an*30) ----
    float fp = 0.f;
    if (tid < NP) {
        const int p = tid;
        float dp = 0.f, mp = 0.f;
#pragma unroll
        for (int a = 0; a < NA; a++) {
            dp = fmaf(s_A1[a * NP + p], s_w2[a], dp);
            mp = fmaf(s_c[a], s_M[a * NP + p], mp);
        }
        fp = dp * mp;
    }
#pragma unroll
    for (int o = 16; o > 0; o >>= 1) fp += __shfl_xor_sync(~0u, fp, o);
    if (lane == 0) s_red[wid] = fp;
    __syncthreads();
    if (tid == 0) {
        float tot = 0.f;
#pragma unroll
        for (int w2 = 0; w2 < 8; w2++) tot += s_red[w2];
        out_sim[t * NB + v] = tot / (s_an[0] * (float)NA);
    }
}

// ---------------------------------------------------------------------------
extern "C" void kernel_launch(void* const* d_in, const int* in_sizes, int n_in,
                              void* d_out, int out_size)
{
    const float* vf      = (const float*)d_in[0];
    const float* tf      = (const float*)d_in[1];
    const int*   mask    = (const int*)d_in[2];
    const int*   att_num = (const int*)d_in[3];
    const float* W_vis   = (const float*)d_in[4];
    const float* b_vis   = (const float*)d_in[5];
    const float* W_txt   = (const float*)d_in[6];
    const float* b_txt   = (const float*)d_in[7];
    const float* W_patch = (const float*)d_in[8];
    const float* b_patch = (const float*)d_in[9];
    const float* W_att   = (const float*)d_in[10];
    const float* b_att   = (const float*)d_in[11];
    float* out = (float*)d_out;

    dim3 blk(256);
    // 1: weight transposes (seg order: patch, att, vis, txt)
    wt_kernel<<<dim3(24, 8, 4), blk>>>(W_patch, W_att, W_vis, W_txt);
    // 2: merged projections, triple-buffered cp.async
    const int proj_smem = 3 * (PA_SZ + PB_SZ) * 4;
    cudaFuncSetAttribute(proj2_kernel, cudaFuncAttributeMaxDynamicSharedMemorySize,
                         proj_smem);
    proj2_kernel<<<dim3(4, 113), blk, proj_smem>>>(vf, tf, b_patch, b_att,
                                                   b_vis, b_txt, out);
    // 3: fused prep (transpose + norms + gram + means)
    prep_kernel<<<2488, blk>>>(att_num, out);
    // 4: fused pair kernel (3 CTAs/SM)
    const int smem_bytes = SMEM_F * 4;
    cudaFuncSetAttribute(pair_kernel, cudaFuncAttributeMaxDynamicSharedMemorySize,
                         smem_bytes);
    pair_kernel<<<dim3(NB, NB), blk, smem_bytes>>>(mask, att_num, out + SIM_OFF);
}